// round 14
// baseline (speedup 1.0000x reference)
#include <cuda_runtime.h>
#include <cstdint>

#define BB 512
#define NN 128
#define DD 512
#define BN (BB * NN)   // 65536

// ---------------- device scratch (allocation-free rule: __device__ globals) ----
__device__ float g_x1[BN * DD];     // 128 MB
__device__ int   g_idx[BN * 3];
__device__ float g_cnt[BN];
__device__ float g_uv[BB * 2 * DD];
__device__ float g_M[4 * DD];
__device__ float g_wp1[2 * DD * DD];   // layer1 Wl,Wr  tf32 pair-permuted
__device__ float g_wp2[2 * DD * DD];   // layer2 Wl,Wr  tf32 pair-permuted

// ---------------------------------------------------------------------------
__device__ __forceinline__ uint32_t f2tf32(float f) {
    uint32_t r;
    asm("cvt.rna.tf32.f32 %0, %1;" : "=r"(r) : "f"(f));
    return r;
}
__device__ __forceinline__ uint32_t smem_u32(const void* p) {
    uint32_t a;
    asm("{ .reg .u64 t; cvta.to.shared.u64 t, %1; cvt.u32.u64 %0, t; }"
        : "=r"(a) : "l"(p));
    return a;
}

__device__ __forceinline__ void mma_tf32(float* c, const uint32_t* a, const uint32_t* b) {
    asm volatile(
        "mma.sync.aligned.m16n8k8.row.col.f32.tf32.tf32.f32 "
        "{%0,%1,%2,%3}, {%4,%5,%6,%7}, {%8,%9}, {%0,%1,%2,%3};"
        : "+f"(c[0]), "+f"(c[1]), "+f"(c[2]), "+f"(c[3])
        : "r"(a[0]), "r"(a[1]), "r"(a[2]), "r"(a[3]), "r"(b[0]), "r"(b[1]));
}

// ---------------------------------------------------------------------------
// kNN on tensor cores (round-13 16-warp config + unroll-2 main loop).
// ---------------------------------------------------------------------------
#define KRSTRIDE 160
#define KTILE    (128 * KRSTRIDE)          // 20480
#define SIMSTR   129
#define SIM_OFF  (4 * KTILE)               // hi bufs 0,1 ; lo bufs 2,3
#define SMEM_KNN (SIM_OFF + 128 * SIMSTR * 4)   // 147968

__global__ void __launch_bounds__(512, 1) knn_tc(const float* __restrict__ x,
                                                 int* __restrict__ idx_out,
                                                 float* __restrict__ cnt) {
    extern __shared__ __align__(16) char dsm[];
    float* simS = (float*)(dsm + SIM_OFF);
    __shared__ int   csh[NN];
    __shared__ float rsinv[NN];

    const int b   = blockIdx.x;
    const int tid = threadIdx.x;
    const int wid = tid >> 5, lane = tid & 31;
    const int g   = lane >> 2, tg = lane & 3;
    const int wm  = wid & 3;            // M quarter (32 rows)
    const int wn  = wid >> 2;           // N quarter (32 cols)
    const float* xb = x + (size_t)b * NN * DD;

    if (tid < NN) csh[tid] = 0;

    const int prow = tid >> 2;
    const int pks  = tid & 3;
    const float* xp = xb + (size_t)prow * DD + pks * 8;

    float acc[2][4][4];
    #pragma unroll
    for (int i = 0; i < 2; ++i)
        #pragma unroll
        for (int j = 0; j < 4; ++j)
            #pragma unroll
            for (int r = 0; r < 4; ++r) acc[i][j][r] = 0.f;

    float4 pa[2];
    auto prefetch = [&](int it) {
        pa[0] = *(const float4*)(xp + it * 32);
        pa[1] = *(const float4*)(xp + it * 32 + 4);
    };

    auto split = [&](float f, uint32_t& hw, uint32_t& lw) {
        hw = f2tf32(f);
        lw = f2tf32(f - __uint_as_float(hw));
    };
    auto store = [&](int buf) {
        char* baseH = dsm + buf * KTILE + prow * KRSTRIDE + pks * 32;
        char* baseL = baseH + 2 * KTILE;
        uint4 h0, h1, l0, l1;
        split(pa[0].x, h0.x, l0.x); split(pa[1].x, h0.y, l0.y);
        split(pa[0].y, h0.z, l0.z); split(pa[1].y, h0.w, l0.w);
        split(pa[0].z, h1.x, l1.x); split(pa[1].z, h1.y, l1.y);
        split(pa[0].w, h1.z, l1.z); split(pa[1].w, h1.w, l1.w);
        *(uint4*)(baseH)      = h0;
        *(uint4*)(baseH + 16) = h1;
        *(uint4*)(baseL)      = l0;
        *(uint4*)(baseL + 16) = l1;
    };

    prefetch(0);
    store(0);
    __syncthreads();

    const char* aRd0 = dsm + (wm * 32 + g) * KRSTRIDE + tg * 8;
    const char* bRd0 = dsm + (wn * 32 + g) * KRSTRIDE + tg * 8;

    #pragma unroll 2
    for (int it = 0; it < 16; ++it) {
        const int buf = it & 1;
        const char* AbH = aRd0 + buf * KTILE;
        const char* BbH = bRd0 + buf * KTILE;

        if (it < 15) prefetch(it + 1);

        #pragma unroll
        for (int ks = 0; ks < 4; ++ks) {
            uint32_t afH[2][4], afL[2][4], bfH[4][2], bfL[4][2];
            #pragma unroll
            for (int mf = 0; mf < 2; ++mf) {
                const char* p = AbH + mf * 16 * KRSTRIDE + ks * 32;
                uint2 h02 = *(const uint2*)(p);
                uint2 h13 = *(const uint2*)(p + 8 * KRSTRIDE);
                uint2 l02 = *(const uint2*)(p + 2 * KTILE);
                uint2 l13 = *(const uint2*)(p + 2 * KTILE + 8 * KRSTRIDE);
                afH[mf][0] = h02.x; afH[mf][1] = h13.x;
                afH[mf][2] = h02.y; afH[mf][3] = h13.y;
                afL[mf][0] = l02.x; afL[mf][1] = l13.x;
                afL[mf][2] = l02.y; afL[mf][3] = l13.y;
            }
            #pragma unroll
            for (int nf = 0; nf < 4; ++nf) {
                const char* p = BbH + nf * 8 * KRSTRIDE + ks * 32;
                uint2 hv = *(const uint2*)(p);
                uint2 lv = *(const uint2*)(p + 2 * KTILE);
                bfH[nf][0] = hv.x; bfH[nf][1] = hv.y;
                bfL[nf][0] = lv.x; bfL[nf][1] = lv.y;
            }
            #pragma unroll
            for (int mf = 0; mf < 2; ++mf)
                #pragma unroll
                for (int nf = 0; nf < 4; ++nf) {
                    mma_tf32(acc[mf][nf], afH[mf], bfL[nf]);   // hi.lo
                    mma_tf32(acc[mf][nf], afL[mf], bfH[nf]);   // lo.hi
                    mma_tf32(acc[mf][nf], afH[mf], bfH[nf]);   // hi.hi
                }
        }

        if (it < 15) store(buf ^ 1);
        __syncthreads();
    }

    // write Gram to simS
    #pragma unroll
    for (int mf = 0; mf < 2; ++mf) {
        const int r0 = wm * 32 + mf * 16 + g;
        #pragma unroll
        for (int nf = 0; nf < 4; ++nf) {
            const int c0 = wn * 32 + nf * 8 + tg * 2;
            simS[(size_t)r0 * SIMSTR + c0]           = acc[mf][nf][0];
            simS[(size_t)r0 * SIMSTR + c0 + 1]       = acc[mf][nf][1];
            simS[(size_t)(r0 + 8) * SIMSTR + c0]     = acc[mf][nf][2];
            simS[(size_t)(r0 + 8) * SIMSTR + c0 + 1] = acc[mf][nf][3];
        }
    }
    __syncthreads();

    if (tid < NN) rsinv[tid] = rsqrtf(simS[(size_t)tid * SIMSTR + tid] + 1e-12f);
    __syncthreads();

    if (tid < NN) {
        const float* row = simS + (size_t)tid * SIMSTR;
        int b0 = -1, b1 = -1;
        #pragma unroll
        for (int t = 0; t < 3; ++t) {
            float bvv = -1e30f; int bi = -1;
            for (int j = 0; j < NN; ++j) {
                if (j == b0 || j == b1) continue;
                float v = row[j] * rsinv[j];
                if (v > bvv) { bvv = v; bi = j; }   // strict '>' == stable tie-break
            }
            idx_out[((size_t)b * NN + tid) * 3 + t] = bi;
            atomicAdd(&csh[bi], 1);
            if (t == 0) b0 = bi; else if (t == 1) b1 = bi;
        }
    }
    __syncthreads();
    if (tid < NN) cnt[(size_t)b * NN + tid] = (float)csh[tid];
}

// ---------------------------------------------------------------------------
// W pre-permute + tf32 pre-convert, BOTH layers in one launch.
// blockIdx.x < half: layer 1 -> dst1 ; else layer 2 -> dst2.
// ---------------------------------------------------------------------------
__global__ void wperm2_kernel(const float* __restrict__ w1l, const float* __restrict__ w1r,
                              const float* __restrict__ w2l, const float* __restrict__ w2r,
                              float* __restrict__ dst1, float* __restrict__ dst2) {
    const int half = 2 * DD * (DD / 2) / 256;       // blocks per layer
    const int layer = blockIdx.x >= half;
    const int id = (blockIdx.x - layer * half) * blockDim.x + threadIdx.x;
    const int rI = id >> 8;
    const int p  = id & 255;
    const int c  = p >> 4, gj = p & 15, g8 = gj >> 2, j = gj & 3;
    const float* W = (rI < DD) ? (layer ? w2l : w1l) : (layer ? w2r : w1r);
    float* dst = layer ? dst2 : dst1;
    const int r = rI & (DD - 1);
    const int k = c * 32 + g8 * 8 + j;
    dst[(size_t)rI * DD + c * 32 + g8 * 8 + j * 2]     = __uint_as_float(f2tf32(W[(size_t)r * DD + k]));
    dst[(size_t)rI * DD + c * 32 + g8 * 8 + j * 2 + 1] = __uint_as_float(f2tf32(W[(size_t)r * DD + k + 4]));
}

// ---------------------------------------------------------------------------
// tf32 mma.sync fused SAGE layer (round-12 structure + unroll-2 main loop):
//  mode 1: leaky + store to out (layer 1)
//  mode 2: leaky + fused u/v pooled reduction to uvOut; NO gmem x2 (layer 2)
// ---------------------------------------------------------------------------
#define RSTRIDE 160
#define A_TILE  (128 * RSTRIDE)          // 20480
#define B_TILE  (256 * RSTRIDE)          // 40960
#define BUFSZ   (A_TILE + B_TILE)        // 61440
#define SMEM_DYN (2 * BUFSZ)             // 122880

__global__ void __launch_bounds__(512, 1) sage_mma(const float* __restrict__ Xsrc,
                                                   const int* __restrict__ idx,
                                                   const float* __restrict__ Wp,
                                                   const float* __restrict__ bias,
                                                   const float* __restrict__ cntp,
                                                   float* __restrict__ out,
                                                   float* __restrict__ uvOut,
                                                   int mode) {
    extern __shared__ __align__(16) char dsm[];
    __shared__ int   idxs[NN * 3];
    __shared__ float cs[NN];
    __shared__ float redU[4 * 256];
    __shared__ float redV[4 * 256];

    const int tid  = threadIdx.x;
    const int wid  = tid >> 5, lane = tid & 31;
    const int g    = lane >> 2, tg = lane & 3;
    const int wm   = wid & 3;            // M quarter (32 rows)
    const int wn   = wid >> 2;           // N quarter (64 cols)
    const int oBase = blockIdx.x * 256;
    const int b     = blockIdx.y;        // M tile == batch
    const float* xb = Xsrc + (size_t)b * NN * DD;
    const uint32_t sb = smem_u32(dsm);

    if (tid < NN * 3) idxs[tid] = idx[(size_t)b * NN * 3 + tid];
    if (mode == 2 && tid >= NN * 3 && tid < NN * 3 + NN)
        cs[tid - NN * 3] = cntp[(size_t)b * NN + (tid - NN * 3)];
    __syncthreads();

    const int prow = tid >> 2;
    const int pks  = tid & 3;
    const int j0 = idxs[prow * 3], j1 = idxs[prow * 3 + 1], j2 = idxs[prow * 3 + 2];
    const float* a0p = xb + (size_t)j0 * DD + pks * 8;
    const float* a1p = xb + (size_t)j1 * DD + pks * 8;
    const float* a2p = xb + (size_t)j2 * DD + pks * 8;
    const float* aSp = xb + (size_t)prow * DD + pks * 8;
    const float inv3 = 1.f / 3.f;

    const int brow = tid >> 1, bhalf = tid & 1;
    const uint32_t bDst0 = sb + A_TILE + brow * RSTRIDE + bhalf * 64;

    float acc[2][8][4];
    #pragma unroll
    for (int i = 0; i < 2; ++i)
        #pragma unroll
        for (int j = 0; j < 8; ++j)
            #pragma unroll
            for (int r = 0; r < 4; ++r) acc[i][j][r] = 0.f;

    float4 pa[2];

    auto prefetchA = [&](int it) {
        const int k0 = (it & 15) * 32;
        if (it < 16) {
            #pragma unroll
            for (int jj = 0; jj < 2; ++jj) {
                float4 a = *(const float4*)(a0p + k0 + jj * 4);
                float4 c = *(const float4*)(a1p + k0 + jj * 4);
                float4 d = *(const float4*)(a2p + k0 + jj * 4);
                pa[jj].x = (a.x + c.x + d.x) * inv3;
                pa[jj].y = (a.y + c.y + d.y) * inv3;
                pa[jj].z = (a.z + c.z + d.z) * inv3;
                pa[jj].w = (a.w + c.w + d.w) * inv3;
            }
        } else {
            pa[0] = *(const float4*)(aSp + k0);
            pa[1] = *(const float4*)(aSp + k0 + 4);
        }
    };
    auto storeA = [&](int buf) {
        uint4 q0, q1;
        q0.x = f2tf32(pa[0].x); q0.y = f2tf32(pa[1].x);
        q0.z = f2tf32(pa[0].y); q0.w = f2tf32(pa[1].y);
        q1.x = f2tf32(pa[0].z); q1.y = f2tf32(pa[1].z);
        q1.z = f2tf32(pa[0].w); q1.w = f2tf32(pa[1].w);
        char* base = dsm + buf * BUFSZ + prow * RSTRIDE + pks * 32;
        *(uint4*)(base)      = q0;
        *(uint4*)(base + 16) = q1;
    };
    auto cpB = [&](int it, int buf) {
        const int part = it >> 4;
        const int c    = it & 15;
        const float* src = Wp + (size_t)(part * DD + oBase + brow) * DD + c * 32 + bhalf * 16;
        uint32_t dst = bDst0 + buf * BUFSZ;
        asm volatile(
            "cp.async.ca.shared.global [%0], [%1], 16;\n"
            "cp.async.ca.shared.global [%2], [%3], 16;\n"
            "cp.async.ca.shared.global [%4], [%5], 16;\n"
            "cp.async.ca.shared.global [%6], [%7], 16;\n"
            :: "r"(dst), "l"(src), "r"(dst + 16), "l"(src + 4),
               "r"(dst + 32), "l"(src + 8), "r"(dst + 48), "l"(src + 12)
            : "memory");
        asm volatile("cp.async.commit_group;\n" ::: "memory");
    };

    // prologue: chunk 0 -> buffer 0
    cpB(0, 0);
    prefetchA(0);
    storeA(0);
    asm volatile("cp.async.wait_group 0;\n" ::: "memory");
    __syncthreads();

    const char* aRd0 = dsm + (wm * 32 + g) * RSTRIDE + tg * 8;
    const char* bRd0 = dsm + A_TILE + (wn * 64 + g) * RSTRIDE + tg * 8;

    #pragma unroll 2
    for (int it = 0; it < 32; ++it) {
        const int buf = it & 1;
        const char* Ab = aRd0 + buf * BUFSZ;
        const char* Bb = bRd0 + buf * BUFSZ;

        if (it < 31) {
            cpB(it + 1, buf ^ 1);
            prefetchA(it + 1);
        }

        #pragma unroll
        for (int ks = 0; ks < 4; ++ks) {
            uint32_t af[2][4], bf[8][2];
            #pragma unroll
            for (int mf = 0; mf < 2; ++mf) {
                uint2 a02 = *(const uint2*)(Ab + mf * 16 * RSTRIDE + ks * 32);
                uint2 a13 = *(const uint2*)(Ab + mf * 16 * RSTRIDE + 8 * RSTRIDE + ks * 32);
                af[mf][0] = a02.x; af[mf][1] = a13.x;
                af[mf][2] = a02.y; af[mf][3] = a13.y;
            }
            #pragma unroll
            for (int nf = 0; nf < 8; ++nf) {
                uint2 bv = *(const uint2*)(Bb + nf * 8 * RSTRIDE + ks * 32);
                bf[nf][0] = bv.x; bf[nf][1] = bv.y;
            }
            #pragma unroll
            for (int mf = 0; mf < 2; ++mf)
                #pragma unroll
                for (int nf = 0; nf < 8; ++nf)
                    mma_tf32(acc[mf][nf], af[mf], bf[nf]);
        }

        if (it < 31) {
            storeA(buf ^ 1);
            asm volatile("cp.async.wait_group 0;\n" ::: "memory");
        }
        __syncthreads();
    }

    if (mode == 1) {
        #pragma unroll
        for (int mf = 0; mf < 2; ++mf) {
            const int row0 = b * NN + wm * 32 + mf * 16 + g;
            #pragma unroll
            for (int nf = 0; nf < 8; ++nf) {
                const int col = oBase + wn * 64 + nf * 8 + tg * 2;
                const float b0 = bias[col], b1 = bias[col + 1];
                float v0 = acc[mf][nf][0] + b0;
                float v1 = acc[mf][nf][1] + b1;
                float v2 = acc[mf][nf][2] + b0;
                float v3 = acc[mf][nf][3] + b1;
                v0 = v0 >= 0.f ? v0 : 0.2f * v0;
                v1 = v1 >= 0.f ? v1 : 0.2f * v1;
                v2 = v2 >= 0.f ? v2 : 0.2f * v2;
                v3 = v3 >= 0.f ? v3 : 0.2f * v3;
                float2 lo; lo.x = v0; lo.y = v1;
                float2 hi; hi.x = v2; hi.y = v3;
                *(float2*)&out[(size_t)row0 * DD + col]       = lo;
                *(float2*)&out[(size_t)(row0 + 8) * DD + col] = hi;
            }
        }
    } else {
        // fused pooled u/v reduction (x2 never hits gmem)
        float cw[2][2];
        #pragma unroll
        for (int mf = 0; mf < 2; ++mf) {
            cw[mf][0] = cs[wm * 32 + mf * 16 + g];
            cw[mf][1] = cs[wm * 32 + mf * 16 + g + 8];
        }
        #pragma unroll
        for (int nf = 0; nf < 8; ++nf) {
            const int lc = wn * 64 + nf * 8 + tg * 2;
            const float b0 = bias[oBase + lc], b1 = bias[oBase + lc + 1];
            float u0 = 0.f, u1 = 0.f, s0 = 0.f, s1 = 0.f;
            #pragma unroll
            for (int mf = 0; mf < 2; ++mf) {
                float v0 = acc[mf][nf][0] + b0;
                float v1 = acc[mf][nf][1] + b1;
                float v2 = acc[mf][nf][2] + b0;
                float v3 = acc[mf][nf][3] + b1;
                v0 = v0 >= 0.f ? v0 : 0.2f * v0;
                v1 = v1 >= 0.f ? v1 : 0.2f * v1;
                v2 = v2 >= 0.f ? v2 : 0.2f * v2;
                v3 = v3 >= 0.f ? v3 : 0.2f * v3;
                u0 += cw[mf][0] * v0 + cw[mf][1] * v2;
                u1 += cw[mf][0] * v1 + cw[mf][1] * v3;
                s0 += v0 + v2;
                s1 += v1 + v3;
            }
            #pragma unroll
            for (int off = 4; off <= 16; off <<= 1) {
                u0 += __shfl_xor_sync(0xffffffffu, u0, off);
                u1 += __shfl_xor_sync(0xffffffffu, u1, off);
                s0 += __shfl_xor_sync(0xffffffffu, s0, off);
                s1 += __shfl_xor_sync(0xffffffffu, s1, off);
            }
            if (lane < 4) {
                redU[wm * 256 + lc]     = u0;
                redU[wm * 256 + lc + 1] = u1;
                redV[wm * 256 + lc]     = s0;
                redV[wm * 256 + lc + 1] = s1;
            }
        }
        __syncthreads();
        if (tid < 256) {
            float u = redU[tid] + redU[256 + tid] + redU[512 + tid] + redU[768 + tid];
            float v = redV[tid] + redV[256 + tid] + redV[512 + tid] + redV[768 + tid];
            uvOut[(size_t)b * 2 * DD + oBase + tid]      = u * (1.f / (3.f * (float)NN));
            uvOut[(size_t)b * 2 * DD + DD + oBase + tid] = v * (1.f / (float)NN);
        }
    }
}

// ---------------------------------------------------------------------------
__global__ void mlmr_kernel(const float* __restrict__ wc, const float* __restrict__ w3l,
                            const float* __restrict__ w3r, float* __restrict__ M) {
    const int o = blockIdx.x & 1, which = blockIdx.x >> 1;
    const float* W = which ? w3r : w3l;
    const int d = threadIdx.x;
    float s = 0.f;
    #pragma unroll 8
    for (int e = 0; e < DD; ++e) s += wc[o * DD + e] * W[(size_t)e * DD + d];
    M[which * 2 * DD + o * DD + d] = s;
}

__global__ void final_kernel(const float* __restrict__ uv, const float* __restrict__ M,
                             const float* __restrict__ wc, const float* __restrict__ b3l,
                             const float* __restrict__ bc, float* __restrict__ out) {
    const int b = blockIdx.x, t = threadIdx.x;
    const float u = uv[(size_t)b * 2 * DD + t];
    const float v = uv[(size_t)b * 2 * DD + DD + t];
    const float bl = b3l[t];
    float s0 = u * M[t]      + v * M[2 * DD + t] + wc[t] * bl;
    float s1 = u * M[DD + t] + v * M[3 * DD + t] + wc[DD + t] * bl;
    #pragma unroll
    for (int off = 16; off; off >>= 1) {
        s0 += __shfl_xor_sync(0xffffffffu, s0, off);
        s1 += __shfl_xor_sync(0xffffffffu, s1, off);
    }
    __shared__ float r0[16], r1[16];
    const int warp = t >> 5, lane = t & 31;
    if (lane == 0) { r0[warp] = s0; r1[warp] = s1; }
    __syncthreads();
    if (t == 0) {
        float t0 = 0.f, t1 = 0.f;
        #pragma unroll
        for (int w = 0; w < 16; ++w) { t0 += r0[w]; t1 += r1[w]; }
        out[b * 2 + 0] = t0 + bc[0];
        out[b * 2 + 1] = t1 + bc[1];
    }
}

// ---------------------------------------------------------------------------
extern "C" void kernel_launch(void* const* d_in, const int* in_sizes, int n_in,
                              void* d_out, int out_size) {
    const float* enc = (const float*)d_in[0];
    const float* w1l = (const float*)d_in[1];
    const float* b1l = (const float*)d_in[2];
    const float* w1r = (const float*)d_in[3];
    const float* w2l = (const float*)d_in[4];
    const float* b2l = (const float*)d_in[5];
    const float* w2r = (const float*)d_in[6];
    const float* w3l = (const float*)d_in[7];
    const float* b3l = (const float*)d_in[8];
    const float* w3r = (const float*)d_in[9];
    const float* wc  = (const float*)d_in[10];
    const float* bc  = (const float*)d_in[11];
    float* out = (float*)d_out;

    float *x1, *cntp, *uvp, *Mp, *wp1, *wp2;
    int* idxp;
    cudaGetSymbolAddress((void**)&x1,   g_x1);
    cudaGetSymbolAddress((void**)&idxp, g_idx);
    cudaGetSymbolAddress((void**)&cntp, g_cnt);
    cudaGetSymbolAddress((void**)&uvp,  g_uv);
    cudaGetSymbolAddress((void**)&Mp,   g_M);
    cudaGetSymbolAddress((void**)&wp1,  g_wp1);
    cudaGetSymbolAddress((void**)&wp2,  g_wp2);

    cudaFuncSetAttribute(sage_mma, cudaFuncAttributeMaxDynamicSharedMemorySize, SMEM_DYN);
    cudaFuncSetAttribute(knn_tc,  cudaFuncAttributeMaxDynamicSharedMemorySize, SMEM_KNN);

    // kNN graph + both W pre-permutations (one launch)
    knn_tc<<<BB, 512, SMEM_KNN>>>(enc, idxp, cntp);
    wperm2_kernel<<<2 * (2 * DD * (DD / 2) / 256), 256>>>(w1l, w1r, w2l, w2r, wp1, wp2);

    // layer 1: leaky + store x1
    sage_mma<<<dim3(2, BB), 512, SMEM_DYN>>>(enc, idxp, wp1, b1l, cntp, x1, uvp, 1);
    // layer 2: leaky + fused u/v pooled reduction (no x2 gmem traffic)
    sage_mma<<<dim3(2, BB), 512, SMEM_DYN>>>(x1, idxp, wp2, b2l, cntp, x1, uvp, 2);

    // layer 3 + mean-pool + classifier, algebraically collapsed
    mlmr_kernel<<<4, DD>>>(wc, w3l, w3r, Mp);
    final_kernel<<<BB, DD>>>(uvp, Mp, wc, b3l, bc, out);
}

// round 15
// speedup vs baseline: 1.0084x; 1.0084x over previous
#include <cuda_runtime.h>
#include <cstdint>

#define BB 512
#define NN 128
#define DD 512
#define BN (BB * NN)   // 65536

// ---------------- device scratch (allocation-free rule: __device__ globals) ----
__device__ float g_x1[BN * DD];     // 128 MB
__device__ int   g_idx[BN * 3];
__device__ float g_cnt[BN];
__device__ float g_uv[BB * 2 * DD];
__device__ float g_M[4 * DD];
__device__ float g_wp1[2 * DD * DD];   // layer1 Wl,Wr  tf32 pair-permuted
__device__ float g_wp2[2 * DD * DD];   // layer2 Wl,Wr  tf32 pair-permuted

// ---------------------------------------------------------------------------
__device__ __forceinline__ uint32_t f2tf32(float f) {
    uint32_t r;
    asm("cvt.rna.tf32.f32 %0, %1;" : "=r"(r) : "f"(f));
    return r;
}
__device__ __forceinline__ uint32_t smem_u32(const void* p) {
    uint32_t a;
    asm("{ .reg .u64 t; cvta.to.shared.u64 t, %1; cvt.u32.u64 %0, t; }"
        : "=r"(a) : "l"(p));
    return a;
}

__device__ __forceinline__ void mma_tf32(float* c, const uint32_t* a, const uint32_t* b) {
    asm volatile(
        "mma.sync.aligned.m16n8k8.row.col.f32.tf32.tf32.f32 "
        "{%0,%1,%2,%3}, {%4,%5,%6,%7}, {%8,%9}, {%0,%1,%2,%3};"
        : "+f"(c[0]), "+f"(c[1]), "+f"(c[2]), "+f"(c[3])
        : "r"(a[0]), "r"(a[1]), "r"(a[2]), "r"(a[3]), "r"(b[0]), "r"(b[1]));
}

// ---------------------------------------------------------------------------
// kNN on tensor cores (round-13 config): 3xTF32 Gram, 16 warps (4x4, 32x32).
// ---------------------------------------------------------------------------
#define KRSTRIDE 160
#define KTILE    (128 * KRSTRIDE)          // 20480
#define SIMSTR   129
#define SIM_OFF  (4 * KTILE)               // hi bufs 0,1 ; lo bufs 2,3
#define SMEM_KNN (SIM_OFF + 128 * SIMSTR * 4)   // 147968

__global__ void __launch_bounds__(512, 1) knn_tc(const float* __restrict__ x,
                                                 int* __restrict__ idx_out,
                                                 float* __restrict__ cnt) {
    extern __shared__ __align__(16) char dsm[];
    float* simS = (float*)(dsm + SIM_OFF);
    __shared__ int   csh[NN];
    __shared__ float rsinv[NN];

    const int b   = blockIdx.x;
    const int tid = threadIdx.x;
    const int wid = tid >> 5, lane = tid & 31;
    const int g   = lane >> 2, tg = lane & 3;
    const int wm  = wid & 3;            // M quarter (32 rows)
    const int wn  = wid >> 2;           // N quarter (32 cols)
    const float* xb = x + (size_t)b * NN * DD;

    if (tid < NN) csh[tid] = 0;

    const int prow = tid >> 2;
    const int pks  = tid & 3;
    const float* xp = xb + (size_t)prow * DD + pks * 8;

    float acc[2][4][4];
    #pragma unroll
    for (int i = 0; i < 2; ++i)
        #pragma unroll
        for (int j = 0; j < 4; ++j)
            #pragma unroll
            for (int r = 0; r < 4; ++r) acc[i][j][r] = 0.f;

    float4 pa[2];
    auto prefetch = [&](int it) {
        pa[0] = *(const float4*)(xp + it * 32);
        pa[1] = *(const float4*)(xp + it * 32 + 4);
    };

    auto split = [&](float f, uint32_t& hw, uint32_t& lw) {
        hw = f2tf32(f);
        lw = f2tf32(f - __uint_as_float(hw));
    };
    auto store = [&](int buf) {
        char* baseH = dsm + buf * KTILE + prow * KRSTRIDE + pks * 32;
        char* baseL = baseH + 2 * KTILE;
        uint4 h0, h1, l0, l1;
        split(pa[0].x, h0.x, l0.x); split(pa[1].x, h0.y, l0.y);
        split(pa[0].y, h0.z, l0.z); split(pa[1].y, h0.w, l0.w);
        split(pa[0].z, h1.x, l1.x); split(pa[1].z, h1.y, l1.y);
        split(pa[0].w, h1.z, l1.z); split(pa[1].w, h1.w, l1.w);
        *(uint4*)(baseH)      = h0;
        *(uint4*)(baseH + 16) = h1;
        *(uint4*)(baseL)      = l0;
        *(uint4*)(baseL + 16) = l1;
    };

    prefetch(0);
    store(0);
    __syncthreads();

    const char* aRd0 = dsm + (wm * 32 + g) * KRSTRIDE + tg * 8;
    const char* bRd0 = dsm + (wn * 32 + g) * KRSTRIDE + tg * 8;

    #pragma unroll 1
    for (int it = 0; it < 16; ++it) {
        const int buf = it & 1;
        const char* AbH = aRd0 + buf * KTILE;
        const char* BbH = bRd0 + buf * KTILE;

        if (it < 15) prefetch(it + 1);

        #pragma unroll
        for (int ks = 0; ks < 4; ++ks) {
            uint32_t afH[2][4], afL[2][4], bfH[4][2], bfL[4][2];
            #pragma unroll
            for (int mf = 0; mf < 2; ++mf) {
                const char* p = AbH + mf * 16 * KRSTRIDE + ks * 32;
                uint2 h02 = *(const uint2*)(p);
                uint2 h13 = *(const uint2*)(p + 8 * KRSTRIDE);
                uint2 l02 = *(const uint2*)(p + 2 * KTILE);
                uint2 l13 = *(const uint2*)(p + 2 * KTILE + 8 * KRSTRIDE);
                afH[mf][0] = h02.x; afH[mf][1] = h13.x;
                afH[mf][2] = h02.y; afH[mf][3] = h13.y;
                afL[mf][0] = l02.x; afL[mf][1] = l13.x;
                afL[mf][2] = l02.y; afL[mf][3] = l13.y;
            }
            #pragma unroll
            for (int nf = 0; nf < 4; ++nf) {
                const char* p = BbH + nf * 8 * KRSTRIDE + ks * 32;
                uint2 hv = *(const uint2*)(p);
                uint2 lv = *(const uint2*)(p + 2 * KTILE);
                bfH[nf][0] = hv.x; bfH[nf][1] = hv.y;
                bfL[nf][0] = lv.x; bfL[nf][1] = lv.y;
            }
            #pragma unroll
            for (int mf = 0; mf < 2; ++mf)
                #pragma unroll
                for (int nf = 0; nf < 4; ++nf) {
                    mma_tf32(acc[mf][nf], afH[mf], bfL[nf]);   // hi.lo
                    mma_tf32(acc[mf][nf], afL[mf], bfH[nf]);   // lo.hi
                    mma_tf32(acc[mf][nf], afH[mf], bfH[nf]);   // hi.hi
                }
        }

        if (it < 15) store(buf ^ 1);
        __syncthreads();
    }

    // write Gram to simS
    #pragma unroll
    for (int mf = 0; mf < 2; ++mf) {
        const int r0 = wm * 32 + mf * 16 + g;
        #pragma unroll
        for (int nf = 0; nf < 4; ++nf) {
            const int c0 = wn * 32 + nf * 8 + tg * 2;
            simS[(size_t)r0 * SIMSTR + c0]           = acc[mf][nf][0];
            simS[(size_t)r0 * SIMSTR + c0 + 1]       = acc[mf][nf][1];
            simS[(size_t)(r0 + 8) * SIMSTR + c0]     = acc[mf][nf][2];
            simS[(size_t)(r0 + 8) * SIMSTR + c0 + 1] = acc[mf][nf][3];
        }
    }
    __syncthreads();

    if (tid < NN) rsinv[tid] = rsqrtf(simS[(size_t)tid * SIMSTR + tid] + 1e-12f);
    __syncthreads();

    if (tid < NN) {
        const float* row = simS + (size_t)tid * SIMSTR;
        int b0 = -1, b1 = -1;
        #pragma unroll
        for (int t = 0; t < 3; ++t) {
            float bvv = -1e30f; int bi = -1;
            for (int j = 0; j < NN; ++j) {
                if (j == b0 || j == b1) continue;
                float v = row[j] * rsinv[j];
                if (v > bvv) { bvv = v; bi = j; }   // strict '>' == stable tie-break
            }
            idx_out[((size_t)b * NN + tid) * 3 + t] = bi;
            atomicAdd(&csh[bi], 1);
            if (t == 0) b0 = bi; else if (t == 1) b1 = bi;
        }
    }
    __syncthreads();
    if (tid < NN) cnt[(size_t)b * NN + tid] = (float)csh[tid];
}

// ---------------------------------------------------------------------------
// W pre-permute + tf32 pre-convert, BOTH layers in one launch.
// ---------------------------------------------------------------------------
__global__ void wperm2_kernel(const float* __restrict__ w1l, const float* __restrict__ w1r,
                              const float* __restrict__ w2l, const float* __restrict__ w2r,
                              float* __restrict__ dst1, float* __restrict__ dst2) {
    const int half = 2 * DD * (DD / 2) / 256;       // blocks per layer
    const int layer = blockIdx.x >= half;
    const int id = (blockIdx.x - layer * half) * blockDim.x + threadIdx.x;
    const int rI = id >> 8;
    const int p  = id & 255;
    const int c  = p >> 4, gj = p & 15, g8 = gj >> 2, j = gj & 3;
    const float* W = (rI < DD) ? (layer ? w2l : w1l) : (layer ? w2r : w1r);
    float* dst = layer ? dst2 : dst1;
    const int r = rI & (DD - 1);
    const int k = c * 32 + g8 * 8 + j;
    dst[(size_t)rI * DD + c * 32 + g8 * 8 + j * 2]     = __uint_as_float(f2tf32(W[(size_t)r * DD + k]));
    dst[(size_t)rI * DD + c * 32 + g8 * 8 + j * 2 + 1] = __uint_as_float(f2tf32(W[(size_t)r * DD + k + 4]));
}

// ---------------------------------------------------------------------------
// tf32 mma.sync fused SAGE layer (round-13 structure, MODE as template):
//  MODE 1: leaky + store to out (layer 1)
//  MODE 2: leaky + fused u/v pooled reduction to uvOut; NO gmem x2 (layer 2)
// ---------------------------------------------------------------------------
#define RSTRIDE 160
#define A_TILE  (128 * RSTRIDE)          // 20480
#define B_TILE  (256 * RSTRIDE)          // 40960
#define BUFSZ   (A_TILE + B_TILE)        // 61440
#define SMEM_DYN (2 * BUFSZ)             // 122880

template <int MODE>
__global__ void __launch_bounds__(512, 1) sage_mma(const float* __restrict__ Xsrc,
                                                   const int* __restrict__ idx,
                                                   const float* __restrict__ Wp,
                                                   const float* __restrict__ bias,
                                                   const float* __restrict__ cntp,
                                                   float* __restrict__ out,
                                                   float* __restrict__ uvOut) {
    extern __shared__ __align__(16) char dsm[];
    __shared__ int   idxs[NN * 3];
    __shared__ float cs[MODE == 2 ? NN : 1];
    __shared__ float redU[MODE == 2 ? 4 * 256 : 1];
    __shared__ float redV[MODE == 2 ? 4 * 256 : 1];

    const int tid  = threadIdx.x;
    const int wid  = tid >> 5, lane = tid & 31;
    const int g    = lane >> 2, tg = lane & 3;
    const int wm   = wid & 3;            // M quarter (32 rows)
    const int wn   = wid >> 2;           // N quarter (64 cols)
    const int oBase = blockIdx.x * 256;
    const int b     = blockIdx.y;        // M tile == batch
    const float* xb = Xsrc + (size_t)b * NN * DD;
    const uint32_t sb = smem_u32(dsm);

    if (tid < NN * 3) idxs[tid] = idx[(size_t)b * NN * 3 + tid];
    if (MODE == 2 && tid >= NN * 3 && tid < NN * 3 + NN)
        cs[tid - NN * 3] = cntp[(size_t)b * NN + (tid - NN * 3)];
    __syncthreads();

    const int prow = tid >> 2;
    const int pks  = tid & 3;
    const int j0 = idxs[prow * 3], j1 = idxs[prow * 3 + 1], j2 = idxs[prow * 3 + 2];
    const float* a0p = xb + (size_t)j0 * DD + pks * 8;
    const float* a1p = xb + (size_t)j1 * DD + pks * 8;
    const float* a2p = xb + (size_t)j2 * DD + pks * 8;
    const float* aSp = xb + (size_t)prow * DD + pks * 8;
    const float inv3 = 1.f / 3.f;

    const int brow = tid >> 1, bhalf = tid & 1;
    const uint32_t bDst0 = sb + A_TILE + brow * RSTRIDE + bhalf * 64;

    float acc[2][8][4];
    #pragma unroll
    for (int i = 0; i < 2; ++i)
        #pragma unroll
        for (int j = 0; j < 8; ++j)
            #pragma unroll
            for (int r = 0; r < 4; ++r) acc[i][j][r] = 0.f;

    float4 pa[2];

    auto prefetchA = [&](int it) {
        const int k0 = (it & 15) * 32;
        if (it < 16) {
            #pragma unroll
            for (int jj = 0; jj < 2; ++jj) {
                float4 a = *(const float4*)(a0p + k0 + jj * 4);
                float4 c = *(const float4*)(a1p + k0 + jj * 4);
                float4 d = *(const float4*)(a2p + k0 + jj * 4);
                pa[jj].x = (a.x + c.x + d.x) * inv3;
                pa[jj].y = (a.y + c.y + d.y) * inv3;
                pa[jj].z = (a.z + c.z + d.z) * inv3;
                pa[jj].w = (a.w + c.w + d.w) * inv3;
            }
        } else {
            pa[0] = *(const float4*)(aSp + k0);
            pa[1] = *(const float4*)(aSp + k0 + 4);
        }
    };
    auto storeA = [&](int buf) {
        uint4 q0, q1;
        q0.x = f2tf32(pa[0].x); q0.y = f2tf32(pa[1].x);
        q0.z = f2tf32(pa[0].y); q0.w = f2tf32(pa[1].y);
        q1.x = f2tf32(pa[0].z); q1.y = f2tf32(pa[1].z);
        q1.z = f2tf32(pa[0].w); q1.w = f2tf32(pa[1].w);
        char* base = dsm + buf * BUFSZ + prow * RSTRIDE + pks * 32;
        *(uint4*)(base)      = q0;
        *(uint4*)(base + 16) = q1;
    };
    auto cpB = [&](int it, int buf) {
        const int part = it >> 4;
        const int c    = it & 15;
        const float* src = Wp + (size_t)(part * DD + oBase + brow) * DD + c * 32 + bhalf * 16;
        uint32_t dst = bDst0 + buf * BUFSZ;
        asm volatile(
            "cp.async.ca.shared.global [%0], [%1], 16;\n"
            "cp.async.ca.shared.global [%2], [%3], 16;\n"
            "cp.async.ca.shared.global [%4], [%5], 16;\n"
            "cp.async.ca.shared.global [%6], [%7], 16;\n"
            :: "r"(dst), "l"(src), "r"(dst + 16), "l"(src + 4),
               "r"(dst + 32), "l"(src + 8), "r"(dst + 48), "l"(src + 12)
            : "memory");
        asm volatile("cp.async.commit_group;\n" ::: "memory");
    };

    // prologue: chunk 0 -> buffer 0
    cpB(0, 0);
    prefetchA(0);
    storeA(0);
    asm volatile("cp.async.wait_group 0;\n" ::: "memory");
    __syncthreads();

    const char* aRd0 = dsm + (wm * 32 + g) * RSTRIDE + tg * 8;
    const char* bRd0 = dsm + A_TILE + (wn * 64 + g) * RSTRIDE + tg * 8;

    #pragma unroll 1
    for (int it = 0; it < 32; ++it) {
        const int buf = it & 1;
        const char* Ab = aRd0 + buf * BUFSZ;
        const char* Bb = bRd0 + buf * BUFSZ;

        if (it < 31) {
            cpB(it + 1, buf ^ 1);
            prefetchA(it + 1);
        }

        #pragma unroll
        for (int ks = 0; ks < 4; ++ks) {
            uint32_t af[2][4], bf[8][2];
            #pragma unroll
            for (int mf = 0; mf < 2; ++mf) {
                uint2 a02 = *(const uint2*)(Ab + mf * 16 * RSTRIDE + ks * 32);
                uint2 a13 = *(const uint2*)(Ab + mf * 16 * RSTRIDE + 8 * RSTRIDE + ks * 32);
                af[mf][0] = a02.x; af[mf][1] = a13.x;
                af[mf][2] = a02.y; af[mf][3] = a13.y;
            }
            #pragma unroll
            for (int nf = 0; nf < 8; ++nf) {
                uint2 bv = *(const uint2*)(Bb + nf * 8 * RSTRIDE + ks * 32);
                bf[nf][0] = bv.x; bf[nf][1] = bv.y;
            }
            #pragma unroll
            for (int mf = 0; mf < 2; ++mf)
                #pragma unroll
                for (int nf = 0; nf < 8; ++nf)
                    mma_tf32(acc[mf][nf], af[mf], bf[nf]);
        }

        if (it < 31) {
            storeA(buf ^ 1);
            asm volatile("cp.async.wait_group 0;\n" ::: "memory");
        }
        __syncthreads();
    }

    if (MODE == 1) {
        #pragma unroll
        for (int mf = 0; mf < 2; ++mf) {
            const int row0 = b * NN + wm * 32 + mf * 16 + g;
            #pragma unroll
            for (int nf = 0; nf < 8; ++nf) {
                const int col = oBase + wn * 64 + nf * 8 + tg * 2;
                const float b0 = bias[col], b1 = bias[col + 1];
                float v0 = acc[mf][nf][0] + b0;
                float v1 = acc[mf][nf][1] + b1;
                float v2 = acc[mf][nf][2] + b0;
                float v3 = acc[mf][nf][3] + b1;
                v0 = v0 >= 0.f ? v0 : 0.2f * v0;
                v1 = v1 >= 0.f ? v1 : 0.2f * v1;
                v2 = v2 >= 0.f ? v2 : 0.2f * v2;
                v3 = v3 >= 0.f ? v3 : 0.2f * v3;
                float2 lo; lo.x = v0; lo.y = v1;
                float2 hi; hi.x = v2; hi.y = v3;
                *(float2*)&out[(size_t)row0 * DD + col]       = lo;
                *(float2*)&out[(size_t)(row0 + 8) * DD + col] = hi;
            }
        }
    } else {
        // fused pooled u/v reduction (x2 never hits gmem)
        float cw[2][2];
        #pragma unroll
        for (int mf = 0; mf < 2; ++mf) {
            cw[mf][0] = cs[wm * 32 + mf * 16 + g];
            cw[mf][1] = cs[wm * 32 + mf * 16 + g + 8];
        }
        #pragma unroll
        for (int nf = 0; nf < 8; ++nf) {
            const int lc = wn * 64 + nf * 8 + tg * 2;
            const float b0 = bias[oBase + lc], b1 = bias[oBase + lc + 1];
            float u0 = 0.f, u1 = 0.f, s0 = 0.f, s1 = 0.f;
            #pragma unroll
            for (int mf = 0; mf < 2; ++mf) {
                float v0 = acc[mf][nf][0] + b0;
                float v1 = acc[mf][nf][1] + b1;
                float v2 = acc[mf][nf][2] + b0;
                float v3 = acc[mf][nf][3] + b1;
                v0 = v0 >= 0.f ? v0 : 0.2f * v0;
                v1 = v1 >= 0.f ? v1 : 0.2f * v1;
                v2 = v2 >= 0.f ? v2 : 0.2f * v2;
                v3 = v3 >= 0.f ? v3 : 0.2f * v3;
                u0 += cw[mf][0] * v0 + cw[mf][1] * v2;
                u1 += cw[mf][0] * v1 + cw[mf][1] * v3;
                s0 += v0 + v2;
                s1 += v1 + v3;
            }
            #pragma unroll
            for (int off = 4; off <= 16; off <<= 1) {
                u0 += __shfl_xor_sync(0xffffffffu, u0, off);
                u1 += __shfl_xor_sync(0xffffffffu, u1, off);
                s0 += __shfl_xor_sync(0xffffffffu, s0, off);
                s1 += __shfl_xor_sync(0xffffffffu, s1, off);
            }
            if (lane < 4) {
                redU[wm * 256 + lc]     = u0;
                redU[wm * 256 + lc + 1] = u1;
                redV[wm * 256 + lc]     = s0;
                redV[wm * 256 + lc + 1] = s1;
            }
        }
        __syncthreads();
        if (tid < 256) {
            float u = redU[tid] + redU[256 + tid] + redU[512 + tid] + redU[768 + tid];
            float v = redV[tid] + redV[256 + tid] + redV[512 + tid] + redV[768 + tid];
            uvOut[(size_t)b * 2 * DD + oBase + tid]      = u * (1.f / (3.f * (float)NN));
            uvOut[(size_t)b * 2 * DD + DD + oBase + tid] = v * (1.f / (float)NN);
        }
    }
}

// ---------------------------------------------------------------------------
__global__ void mlmr_kernel(const float* __restrict__ wc, const float* __restrict__ w3l,
                            const float* __restrict__ w3r, float* __restrict__ M) {
    const int o = blockIdx.x & 1, which = blockIdx.x >> 1;
    const float* W = which ? w3r : w3l;
    const int d = threadIdx.x;
    float s = 0.f;
    #pragma unroll 8
    for (int e = 0; e < DD; ++e) s += wc[o * DD + e] * W[(size_t)e * DD + d];
    M[which * 2 * DD + o * DD + d] = s;
}

__global__ void final_kernel(const float* __restrict__ uv, const float* __restrict__ M,
                             const float* __restrict__ wc, const float* __restrict__ b3l,
                             const float* __restrict__ bc, float* __restrict__ out) {
    const int b = blockIdx.x, t = threadIdx.x;
    const float u = uv[(size_t)b * 2 * DD + t];
    const float v = uv[(size_t)b * 2 * DD + DD + t];
    const float bl = b3l[t];
    float s0 = u * M[t]      + v * M[2 * DD + t] + wc[t] * bl;
    float s1 = u * M[DD + t] + v * M[3 * DD + t] + wc[DD + t] * bl;
    #pragma unroll
    for (int off = 16; off; off >>= 1) {
        s0 += __shfl_xor_sync(0xffffffffu, s0, off);
        s1 += __shfl_xor_sync(0xffffffffu, s1, off);
    }
    __shared__ float r0[16], r1[16];
    const int warp = t >> 5, lane = t & 31;
    if (lane == 0) { r0[warp] = s0; r1[warp] = s1; }
    __syncthreads();
    if (t == 0) {
        float t0 = 0.f, t1 = 0.f;
        #pragma unroll
        for (int w = 0; w < 16; ++w) { t0 += r0[w]; t1 += r1[w]; }
        out[b * 2 + 0] = t0 + bc[0];
        out[b * 2 + 1] = t1 + bc[1];
    }
}

// ---------------------------------------------------------------------------
extern "C" void kernel_launch(void* const* d_in, const int* in_sizes, int n_in,
                              void* d_out, int out_size) {
    const float* enc = (const float*)d_in[0];
    const float* w1l = (const float*)d_in[1];
    const float* b1l = (const float*)d_in[2];
    const float* w1r = (const float*)d_in[3];
    const float* w2l = (const float*)d_in[4];
    const float* b2l = (const float*)d_in[5];
    const float* w2r = (const float*)d_in[6];
    const float* w3l = (const float*)d_in[7];
    const float* b3l = (const float*)d_in[8];
    const float* w3r = (const float*)d_in[9];
    const float* wc  = (const float*)d_in[10];
    const float* bc  = (const float*)d_in[11];
    float* out = (float*)d_out;

    float *x1, *cntp, *uvp, *Mp, *wp1, *wp2;
    int* idxp;
    cudaGetSymbolAddress((void**)&x1,   g_x1);
    cudaGetSymbolAddress((void**)&idxp, g_idx);
    cudaGetSymbolAddress((void**)&cntp, g_cnt);
    cudaGetSymbolAddress((void**)&uvp,  g_uv);
    cudaGetSymbolAddress((void**)&Mp,   g_M);
    cudaGetSymbolAddress((void**)&wp1,  g_wp1);
    cudaGetSymbolAddress((void**)&wp2,  g_wp2);

    cudaFuncSetAttribute(sage_mma<1>, cudaFuncAttributeMaxDynamicSharedMemorySize, SMEM_DYN);
    cudaFuncSetAttribute(sage_mma<2>, cudaFuncAttributeMaxDynamicSharedMemorySize, SMEM_DYN);
    cudaFuncSetAttribute(knn_tc, cudaFuncAttributeMaxDynamicSharedMemorySize, SMEM_KNN);

    // kNN graph + both W pre-permutations (one launch)
    knn_tc<<<BB, 512, SMEM_KNN>>>(enc, idxp, cntp);
    wperm2_kernel<<<2 * (2 * DD * (DD / 2) / 256), 256>>>(w1l, w1r, w2l, w2r, wp1, wp2);

    // layer 1: leaky + store x1
    sage_mma<1><<<dim3(2, BB), 512, SMEM_DYN>>>(enc, idxp, wp1, b1l, cntp, x1, uvp);
    // layer 2: leaky + fused u/v pooled reduction (no x2 gmem traffic)
    sage_mma<2><<<dim3(2, BB), 512, SMEM_DYN>>>(x1, idxp, wp2, b2l, cntp, x1, uvp);

    // layer 3 + mean-pool + classifier, algebraically collapsed
    mlmr_kernel<<<4, DD>>>(wc, w3l, w3r, Mp);
    final_kernel<<<BB, DD>>>(uvp, Mp, wc, b3l, bc, out);
}